// round 7
// baseline (speedup 1.0000x reference)
#include <cuda_runtime.h>
#include <cuda_bf16.h>
#include <cstdint>

#define IN_      512
#define OUT_     512
#define NB_      16
#define M_TOTAL  1024
#define TM       64
#define TN       64
#define NTHREADS 256

// smem layout (bytes): A bufs (Ah+Al per buf), B bufs (Bh+Bl per buf)
#define PLANE      8192                    // 64 rows * 128 B (64 bf16)
#define ABUF(b)    ((b) * 2 * PLANE)       // 0 / 16384
#define BBUF(b)    (32768 + (b) * 2 * PLANE)
#define OFF_ROWS   65536                   // int rows_bank[1024]
#define OFF_BIAS   (OFF_ROWS + M_TOTAL * 4)
#define SMEM_TOTAL (OFF_BIAS + TN * 4)     // 69888

// preconverted x planes (bf16 hi/lo), row-major [1024][512]
__device__ __align__(16) __nv_bfloat16 g_xh[M_TOTAL * IN_];
__device__ __align__(16) __nv_bfloat16 g_xl[M_TOTAL * IN_];

// ---------------- PTX helpers ----------------
__device__ __forceinline__ uint32_t smem_u32(const void* p) {
    uint32_t a;
    asm("{ .reg .u64 t; cvta.to.shared.u64 t, %1; cvt.u32.u64 %0, t; }" : "=r"(a) : "l"(p));
    return a;
}
__device__ __forceinline__ void ldsm4(uint32_t* r, uint32_t addr) {
    asm volatile("ldmatrix.sync.aligned.m8n8.x4.shared.b16 {%0,%1,%2,%3}, [%4];"
        : "=r"(r[0]), "=r"(r[1]), "=r"(r[2]), "=r"(r[3]) : "r"(addr));
}
__device__ __forceinline__ void mma_bf16(float* c, const uint32_t* a, uint32_t b0, uint32_t b1) {
    asm volatile("mma.sync.aligned.m16n8k16.row.col.f32.bf16.bf16.f32 "
        "{%0,%1,%2,%3}, {%4,%5,%6,%7}, {%8,%9}, {%0,%1,%2,%3};"
        : "+f"(c[0]), "+f"(c[1]), "+f"(c[2]), "+f"(c[3])
        : "r"(a[0]), "r"(a[1]), "r"(a[2]), "r"(a[3]), "r"(b0), "r"(b1));
}
__device__ __forceinline__ void cp_async16(uint32_t dst, const void* src, int srcsize) {
    asm volatile("cp.async.cg.shared.global [%0], [%1], 16, %2;"
        :: "r"(dst), "l"(src), "r"(srcsize) : "memory");
}
#define CP_COMMIT() asm volatile("cp.async.commit_group;" ::: "memory")
#define CP_WAIT(n)  asm volatile("cp.async.wait_group %0;" :: "n"(n) : "memory")

// split float4 -> packed bf16 hi pairs + lo (residual) pairs
__device__ __forceinline__ void split4(float4 v, uint2& hi, uint2& lo) {
    uint32_t h01, h23;
    asm("cvt.rn.bf16x2.f32 %0, %1, %2;" : "=r"(h01) : "f"(v.y), "f"(v.x));
    asm("cvt.rn.bf16x2.f32 %0, %1, %2;" : "=r"(h23) : "f"(v.w), "f"(v.z));
    float f0 = __uint_as_float(h01 << 16);
    float f1 = __uint_as_float(h01 & 0xFFFF0000u);
    float f2 = __uint_as_float(h23 << 16);
    float f3 = __uint_as_float(h23 & 0xFFFF0000u);
    uint32_t l01, l23;
    asm("cvt.rn.bf16x2.f32 %0, %1, %2;" : "=r"(l01) : "f"(v.y - f1), "f"(v.x - f0));
    asm("cvt.rn.bf16x2.f32 %0, %1, %2;" : "=r"(l23) : "f"(v.w - f3), "f"(v.z - f2));
    hi.x = h01; hi.y = h23; lo.x = l01; lo.y = l23;
}

// ---------------- prep kernel: x -> bf16 hi/lo planes ----------------
__global__ __launch_bounds__(256) void convert_x(const float* __restrict__ x) {
    int i = blockIdx.x * 256 + threadIdx.x;        // float4 index
    float4 v = *(const float4*)&x[i * 4];
    uint2 hi, lo;
    split4(v, hi, lo);
    *(uint2*)&g_xh[i * 4] = hi;
    *(uint2*)&g_xl[i * 4] = lo;
}

// ---------------- fused binning + grouped GEMM (bf16-split HMMA) -------------
__global__ __launch_bounds__(NTHREADS, 2) void gemm_kernel(
    const float* __restrict__ x,      // unused (kept for signature stability)
    const int*   __restrict__ sel,    // (1024,)
    const float* __restrict__ w,      // (NB, OUT, IN)
    const float* __restrict__ bias,   // (NB, OUT)
    float* __restrict__ out)          // (1024, OUT)
{
    extern __shared__ __align__(128) uint8_t smem[];
    int*   rows_bank = (int*)(smem + OFF_ROWS);
    float* bias_s    = (float*)(smem + OFF_BIAS);
    __shared__ int warp_base[8];
    __shared__ int cnt_s;

    const int tid = threadIdx.x;
    const int lid = tid & 31, wid = tid >> 5;
    const int warp_m = wid & 3;        // 4 m-warps x 16 rows
    const int warp_n = wid >> 2;       // 2 n-warps x 32 cols
    const int g  = blockIdx.y;
    const int n0 = blockIdx.x * TN;
    const int mz = blockIdx.z;         // m-slice within bank

    // ---- deterministic binning (stable compaction; identical in all CTAs) ----
    {
        int4 sv = *(const int4*)&sel[tid * 4];
        int m0f = (sv.x == g), m1f = (sv.y == g), m2f = (sv.z == g), m3f = (sv.w == g);
        int lc = m0f + m1f + m2f + m3f;
        int inc = lc;
        #pragma unroll
        for (int d = 1; d < 32; d <<= 1) {
            int nv = __shfl_up_sync(0xffffffffu, inc, d);
            if (lid >= d) inc += nv;
        }
        if (lid == 31) warp_base[wid] = inc;
        __syncthreads();
        if (tid == 0) {
            int acc = 0;
            #pragma unroll
            for (int i = 0; i < 8; i++) { int v = warp_base[i]; warp_base[i] = acc; acc += v; }
            cnt_s = acc;
        }
        __syncthreads();
        int p = warp_base[wid] + inc - lc;
        if (m0f) rows_bank[p++] = tid * 4 + 0;
        if (m1f) rows_bank[p++] = tid * 4 + 1;
        if (m2f) rows_bank[p++] = tid * 4 + 2;
        if (m3f) rows_bank[p++] = tid * 4 + 3;
    }
    if (tid < TN) bias_s[tid] = bias[g * OUT_ + n0 + tid];
    __syncthreads();
    const int cnt = cnt_s;
    if (mz * TM >= cnt) return;

    const float* __restrict__ wg = w + (size_t)g * OUT_ * IN_;
    const uint32_t sm_b = smem_u32(smem);

    // ---- A cp.async geometry: 4 x 16B per thread per chunk ----
    uint32_t a_dst[4];               // swizzled dst offset within an A buffer
    int      a_row[4];               // m-tile row (for validity)
    const __nv_bfloat16* a_srcb[4];  // base src (advance by row/k later)
    #pragma unroll
    for (int i = 0; i < 4; i++) {
        int idx = tid + i * 256;
        int plane = idx >> 9;
        int rem   = idx & 511;
        int row   = rem >> 3;
        int c16   = rem & 7;
        uint32_t off = (uint32_t)(row * 128 + c16 * 16);
        a_dst[i] = (uint32_t)(plane * PLANE) + (off ^ ((uint32_t)(row & 7) << 4));
        a_row[i] = row;
        a_srcb[i] = (plane ? g_xl : g_xh) + c16 * 8;
    }

    // ---- B staging geometry: row = tid>>2 (0..63), 16 floats at (tid&3)*16 ----
    // FIX vs R6: swizzle each 16B unit independently (no +16 after XOR).
    const int b_row = tid >> 2;
    const uint32_t b_base = (uint32_t)(b_row * 128 + (tid & 3) * 32);
    const uint32_t b_msk  = (uint32_t)(b_row & 7) << 4;
    const uint32_t b_sw0  = b_base ^ b_msk;
    const uint32_t b_sw1  = (b_base + 16) ^ b_msk;
    const float* __restrict__ b_src = wg + (size_t)(n0 + b_row) * IN_ + (tid & 3) * 16;

    // ldmatrix constant address parts (unchanged from R5)
    const uint32_t swx   = (uint32_t)(lid & 7) * 16;
    const uint32_t khalf = (uint32_t)(lid >> 4) * 16;
    const uint32_t a_off  = (uint32_t)(warp_m * 16 + (lid & 15)) * 128;
    const uint32_t b0_off = (uint32_t)(warp_n * 32 + (lid & 15)) * 128;
    const uint32_t b1_off = b0_off + 16 * 128;

    for (int m0 = mz * TM; m0 < cnt; m0 += 2 * TM) {
        // resolve A source rows + validity for this m-pass
        const __nv_bfloat16* a_src[4];
        int a_sz[4];
        #pragma unroll
        for (int i = 0; i < 4; i++) {
            int m = m0 + a_row[i];
            int valid = (m < cnt);
            int r = valid ? rows_bank[m] : 0;
            a_src[i] = a_srcb[i] + (size_t)r * IN_;
            a_sz[i]  = valid ? 16 : 0;
        }

        // prologue: B chunk 0 -> regs; A chunk 0 -> cp.async buf0
        float4 bv[4];
        #pragma unroll
        for (int j = 0; j < 4; j++) bv[j] = *(const float4*)(b_src + j * 4);
        #pragma unroll
        for (int i = 0; i < 4; i++)
            cp_async16(sm_b + ABUF(0) + a_dst[i], a_src[i], a_sz[i]);
        CP_COMMIT();

        float acc[4][4] = {};

        #pragma unroll 1
        for (int t = 0; t < IN_ / 64; t++) {          // 8 k-chunks of 64
            const int cur = t & 1;

            // issue A(t+1) into the other buffer
            if (t < IN_ / 64 - 1) {
                int k1 = (t + 1) * 64;
                #pragma unroll
                for (int i = 0; i < 4; i++)
                    cp_async16(sm_b + ABUF(1 - cur) + a_dst[i], a_src[i] + k1, a_sz[i]);
                CP_COMMIT();
            }

            // split + store B(t) into bufB(cur) — per-16B swizzled addresses
            {
                uint8_t* bb = smem + BBUF(cur);
                uint2 h0, l0, h1, l1;
                split4(bv[0], h0, l0); split4(bv[1], h1, l1);
                *(uint4*)(bb + b_sw0)         = make_uint4(h0.x, h0.y, h1.x, h1.y);
                *(uint4*)(bb + PLANE + b_sw0) = make_uint4(l0.x, l0.y, l1.x, l1.y);
                split4(bv[2], h0, l0); split4(bv[3], h1, l1);
                *(uint4*)(bb + b_sw1)         = make_uint4(h0.x, h0.y, h1.x, h1.y);
                *(uint4*)(bb + PLANE + b_sw1) = make_uint4(l0.x, l0.y, l1.x, l1.y);
            }
            // prefetch B(t+1) regs
            if (t < IN_ / 64 - 1) {
                const float* s = b_src + (t + 1) * 64;
                #pragma unroll
                for (int j = 0; j < 4; j++) bv[j] = *(const float4*)(s + j * 4);
            }

            // A(t) arrival
            if (t < IN_ / 64 - 1) CP_WAIT(1); else CP_WAIT(0);
            __syncthreads();

            // ---- compute chunk t: 4 k16 steps, 3-product bf16 split ----
            const uint32_t ah_b = sm_b + ABUF(cur) + a_off;
            const uint32_t al_b = ah_b + PLANE;
            const uint32_t bh_b = sm_b + BBUF(cur);
            const uint32_t bl_b = bh_b + PLANE;
            #pragma unroll
            for (int s = 0; s < 4; s++) {
                uint32_t koff = ((uint32_t)(khalf + s * 32)) ^ swx;
                uint32_t ah[4], al[4], bh0[4], bh1[4], bl0[4], bl1[4];
                ldsm4(ah,  ah_b + koff);
                ldsm4(al,  al_b + koff);
                ldsm4(bh0, bh_b + b0_off + koff);
                ldsm4(bh1, bh_b + b1_off + koff);
                ldsm4(bl0, bl_b + b0_off + koff);
                ldsm4(bl1, bl_b + b1_off + koff);

                uint32_t bhx[4][2] = {{bh0[0], bh0[2]}, {bh0[1], bh0[3]},
                                      {bh1[0], bh1[2]}, {bh1[1], bh1[3]}};
                uint32_t blx[4][2] = {{bl0[0], bl0[2]}, {bl0[1], bl0[3]},
                                      {bl1[0], bl1[2]}, {bl1[1], bl1[3]}};
                #pragma unroll
                for (int nf = 0; nf < 4; nf++) {
                    mma_bf16(acc[nf], ah, bhx[nf][0], bhx[nf][1]);  // hi*hi
                    mma_bf16(acc[nf], ah, blx[nf][0], blx[nf][1]);  // hi*lo
                    mma_bf16(acc[nf], al, bhx[nf][0], bhx[nf][1]);  // lo*hi
                }
            }
            __syncthreads();   // compute(t) done before A(t+2)/B(t+1) overwrite
        }

        // ---- epilogue: scatter rows with bias ----
        {
            int gq = lid >> 2, tq = lid & 3;
            int m_lo = m0 + warp_m * 16 + gq;
            int r0 = (m_lo     < cnt) ? rows_bank[m_lo]     : -1;
            int r1 = (m_lo + 8 < cnt) ? rows_bank[m_lo + 8] : -1;
            #pragma unroll
            for (int nf = 0; nf < 4; nf++) {
                int col = warp_n * 32 + nf * 8 + tq * 2;
                float bb0 = bias_s[col], bb1 = bias_s[col + 1];
                if (r0 >= 0) {
                    float2 v = make_float2(acc[nf][0] + bb0, acc[nf][1] + bb1);
                    *(float2*)&out[(size_t)r0 * OUT_ + n0 + col] = v;
                }
                if (r1 >= 0) {
                    float2 v = make_float2(acc[nf][2] + bb0, acc[nf][3] + bb1);
                    *(float2*)&out[(size_t)r1 * OUT_ + n0 + col] = v;
                }
            }
        }
    }
}

// ---------------------------------------------------------------------------
extern "C" void kernel_launch(void* const* d_in, const int* in_sizes, int n_in,
                              void* d_out, int out_size) {
    const float* tensor = (const float*)d_in[0];   // (B,S,K,IN) fp32
    const int*   sel    = (const int*)  d_in[1];   // (B,S,K) int32
    const float* weight = (const float*)d_in[2];   // (NB,OUT,IN) fp32
    const float* bias   = (const float*)d_in[3];   // (NB,OUT) fp32
    float*       out    = (float*)d_out;           // (B,S,K,OUT) fp32

    cudaFuncSetAttribute(gemm_kernel, cudaFuncAttributeMaxDynamicSharedMemorySize, SMEM_TOTAL);
    convert_x<<<M_TOTAL * IN_ / 4 / 256, 256>>>(tensor);
    dim3 grid(OUT_ / TN, NB_, 2);   // (8, 16, 2) = 256 CTAs, one wave @ 2 CTA/SM
    gemm_kernel<<<grid, NTHREADS, SMEM_TOTAL>>>(tensor, sel, weight, bias, out);
}